// round 6
// baseline (speedup 1.0000x reference)
#include <cuda_runtime.h>
#include <cstdint>

// Problem dims (fixed by setup_inputs)
#define T_DIM 1024
#define B_DIM 32
#define D_DIM 768
#define N_DIM 64
#define PROJ_C 256          // 4*n : k | v | q | m
#define M_ROWS (T_DIM * B_DIM)

#define LOG2E 1.4426950408889634f

// Scratch: projection results [T, B, 256] fp32 (~33.5 MB) + per-row scalars
__device__ float  g_proj[(size_t)T_DIM * B_DIM * PROJ_C];
__device__ float4 g_scal[(size_t)T_DIM * B_DIM];   // {kk, mm, km, kq}

// ---------------------------------------------------------------------------
__device__ __forceinline__ float ex2f(float x) {
    float y; asm("ex2.approx.ftz.f32 %0, %1;" : "=f"(y) : "f"(x)); return y;
}
__device__ __forceinline__ float rcpf(float x) {
    float y; asm("rcp.approx.ftz.f32 %0, %1;" : "=f"(y) : "f"(x)); return y;
}
__device__ __forceinline__ float sigmoidf(float x) {   // off-chain uses only
    return rcpf(1.0f + ex2f(-x * LOG2E));
}

// ---------------------------------------------------------------------------
// GEMM: proj[r, c] = sum_d x[r, d] * W[c, d]
//   Tile: 128 (M) x 64 (N), BK = 16, 256 threads, 8x4 per-thread microtile
//   (measured at the fp32 FFMA issue roofline — leave as is)
// ---------------------------------------------------------------------------
__global__ void __launch_bounds__(256, 4)
gemm_kernel(const float* __restrict__ A, const float* __restrict__ W) {
    __shared__ float As[16][132];
    __shared__ float Bs[16][68];

    const int bm = blockIdx.x * 128;
    const int bn = blockIdx.y * 64;
    const int t  = threadIdx.x;
    const int tx = t & 15;
    const int ty = t >> 4;

    float acc[8][4];
#pragma unroll
    for (int x = 0; x < 8; ++x)
#pragma unroll
        for (int y = 0; y < 4; ++y) acc[x][y] = 0.0f;

    for (int k0 = 0; k0 < D_DIM; k0 += 16) {
#pragma unroll
        for (int p = 0; p < 2; ++p) {
            int f   = p * 256 + t;
            int row = f >> 2;
            int kq  = (f & 3) * 4;
            float4 v = *(const float4*)(A + (size_t)(bm + row) * D_DIM + k0 + kq);
            As[kq + 0][row] = v.x; As[kq + 1][row] = v.y;
            As[kq + 2][row] = v.z; As[kq + 3][row] = v.w;
        }
        {
            int row = t >> 2;
            int kq  = (t & 3) * 4;
            float4 v = *(const float4*)(W + (size_t)(bn + row) * D_DIM + k0 + kq);
            Bs[kq + 0][row] = v.x; Bs[kq + 1][row] = v.y;
            Bs[kq + 2][row] = v.z; Bs[kq + 3][row] = v.w;
        }
        __syncthreads();

#pragma unroll
        for (int kk = 0; kk < 16; ++kk) {
            float4 a0 = *(const float4*)&As[kk][ty * 8];
            float4 a1 = *(const float4*)&As[kk][ty * 8 + 4];
            float4 bv = *(const float4*)&Bs[kk][tx * 4];
            float a[8]  = {a0.x, a0.y, a0.z, a0.w, a1.x, a1.y, a1.z, a1.w};
            float bb[4] = {bv.x, bv.y, bv.z, bv.w};
#pragma unroll
            for (int x = 0; x < 8; ++x)
#pragma unroll
                for (int y = 0; y < 4; ++y)
                    acc[x][y] = fmaf(a[x], bb[y], acc[x][y]);
        }
        __syncthreads();
    }

#pragma unroll
    for (int x = 0; x < 8; ++x) {
        float4 v = make_float4(acc[x][0], acc[x][1], acc[x][2], acc[x][3]);
        *(float4*)(g_proj + (size_t)(bm + ty * 8 + x) * PROJ_C + bn + tx * 4) = v;
    }
}

// ---------------------------------------------------------------------------
// Normalize k (cols 0:64) and m (cols 192:256) per (t,b) row; also compute
// per-row scalars kk=<kn,kn>, mm=<mn,mn>, km=<kn,mn>, kq=<kn,q>.
// ---------------------------------------------------------------------------
__global__ void norm_kernel() {
    const int w    = (blockIdx.x * blockDim.x + threadIdx.x) >> 5;
    const int lane = threadIdx.x & 31;
    if (w >= M_ROWS) return;
    float* p = g_proj + (size_t)w * PROJ_C;

    float k0 = p[lane],       k1 = p[lane + 32];
    float q0 = p[128 + lane], q1 = p[160 + lane];
    float m0 = p[192 + lane], m1 = p[224 + lane];

    float sk  = fmaf(k0, k0, k1 * k1);
    float sm  = fmaf(m0, m0, m1 * m1);
    float skm = fmaf(k0, m0, k1 * m1);
    float skq = fmaf(k0, q0, k1 * q1);
#pragma unroll
    for (int o = 16; o > 0; o >>= 1) {
        float a = __shfl_xor_sync(0xffffffffu, sk,  o);
        float b = __shfl_xor_sync(0xffffffffu, sm,  o);
        float c = __shfl_xor_sync(0xffffffffu, skm, o);
        float d = __shfl_xor_sync(0xffffffffu, skq, o);
        sk += a; sm += b; skm += c; skq += d;
    }

    float ck = __fdividef(1.0f, sqrtf(sk) + 1e-6f);
    float cm = __fdividef(1.0f, sqrtf(sm) + 1e-6f);
    p[lane]       = k0 * ck;  p[lane + 32] = k1 * ck;
    p[192 + lane] = m0 * cm;  p[224 + lane] = m1 * cm;

    if (lane == 0) {
        float4 sc;
        sc.x = sk  * ck * ck;
        sc.y = sm  * cm * cm;
        sc.z = skm * ck * cm;
        sc.w = skq * ck;
        g_scal[w] = sc;
    }
}

// ---------------------------------------------------------------------------
// Sequential scan, scalar-space RK4 with software-pipelined dot products.
//
// Timestep map: s <- A*s + B*k, g <- C*g + D*m (exact within-timestep algebra).
// The dots needed at t+1 (of s_{t+1}, g_{t+1} with the NEW k', m', q') expand
// through the rank-1 map into dots of {s,g,k,m}_t with {k',m',q'} — all
// computable BEFORE the scalar chain of timestep t finishes. So per timestep
// the critical path is ONLY the 16-stage scalar recursion; the 10 dots +
// butterflies + rank-1 update fill its stall slots.
//
// Sigmoid on the chain: r, u, km carried pre-scaled by log2(e) so each gate is
// ex2.approx -> 1+e -> rcp.approx (neg folded into consumer FMAs).
//
// Layout: 8 lanes per row, 4 rows per warp, 512 independent warps.
// ---------------------------------------------------------------------------
__global__ void __launch_bounds__(128)
scan_kernel(const float* __restrict__ S0,
            const float* __restrict__ G0,
            const int*   __restrict__ ns_ptr,
            float* __restrict__ out) {
    const int w    = (blockIdx.x * blockDim.x + threadIdx.x) >> 5;
    const int lane = threadIdx.x & 31;
    const int b    = w >> 4;                 // 16 warps per batch
    const int grp  = (lane >> 3);
    const int sub  = lane & 7;
    const int i    = (w & 15) * 4 + grp;     // row 0..63

    const int   ns  = ns_ptr ? *ns_ptr : 4;
    const float dt  = __fdividef(1.0f, (float)ns);
    const float h2  = 0.5f * dt;
    const float hd6 = dt * (1.0f / 6.0f);

    const size_t sbase = ((size_t)b * N_DIM + i) * N_DIM + sub * 8;
    float s[8], g[8];
    {
        float4 a = *(const float4*)(S0 + sbase);
        float4 c = *(const float4*)(S0 + sbase + 4);
        s[0]=a.x; s[1]=a.y; s[2]=a.z; s[3]=a.w; s[4]=c.x; s[5]=c.y; s[6]=c.z; s[7]=c.w;
        float4 e = *(const float4*)(G0 + sbase);
        float4 f = *(const float4*)(G0 + sbase + 4);
        g[0]=e.x; g[1]=e.y; g[2]=e.z; g[3]=e.w; g[4]=f.x; g[5]=f.y; g[6]=f.z; g[7]=f.w;
    }

    // Load t=0 vectors and scalars
    float k[8], m[8], vi;
    float4 sc;
    float p, rL, uL, wv, zz;    // carried chain inputs (rL, uL pre-scaled by LOG2E)
    {
        const float* pp = g_proj + ((size_t)b << 8);
        float4 a0 = *(const float4*)(pp + sub * 8);
        float4 a1 = *(const float4*)(pp + sub * 8 + 4);
        k[0]=a0.x; k[1]=a0.y; k[2]=a0.z; k[3]=a0.w; k[4]=a1.x; k[5]=a1.y; k[6]=a1.z; k[7]=a1.w;
        float4 m0 = *(const float4*)(pp + 192 + sub * 8);
        float4 m1 = *(const float4*)(pp + 192 + sub * 8 + 4);
        m[0]=m0.x; m[1]=m0.y; m[2]=m0.z; m[3]=m0.w; m[4]=m1.x; m[5]=m1.y; m[6]=m1.z; m[7]=m1.w;
        float qv[8];
        float4 q0 = *(const float4*)(pp + 128 + sub * 8);
        float4 q1 = *(const float4*)(pp + 128 + sub * 8 + 4);
        qv[0]=q0.x; qv[1]=q0.y; qv[2]=q0.z; qv[3]=q0.w; qv[4]=q1.x; qv[5]=q1.y; qv[6]=q1.z; qv[7]=q1.w;
        vi = pp[64 + i];
        sc = g_scal[b];

        // Prologue dots: <s,k>, <s,m>, <g,k>, <g,m>, <s,q>
        float d0 = 0.f, d1 = 0.f, d2 = 0.f, d3 = 0.f, d4 = 0.f;
#pragma unroll
        for (int e = 0; e < 8; ++e) {
            d0 = fmaf(s[e], k[e], d0);
            d1 = fmaf(s[e], m[e], d1);
            d2 = fmaf(g[e], k[e], d2);
            d3 = fmaf(g[e], m[e], d3);
            d4 = fmaf(s[e], qv[e], d4);
        }
#pragma unroll
        for (int o = 4; o > 0; o >>= 1) {
            d0 += __shfl_xor_sync(0xffffffffu, d0, o);
            d1 += __shfl_xor_sync(0xffffffffu, d1, o);
            d2 += __shfl_xor_sync(0xffffffffu, d2, o);
            d3 += __shfl_xor_sync(0xffffffffu, d3, o);
            d4 += __shfl_xor_sync(0xffffffffu, d4, o);
        }
        p = d0; rL = LOG2E * d1; uL = LOG2E * d2; wv = d3; zz = d4;
    }

    for (int t = 0; t < T_DIM; ++t) {
        // ---- prefetch next timestep vectors (off-chain) ----
        float nk[8], nm[8], nq[8], nvi = 0.f;
        float4 nsc = sc;
        if (t + 1 < T_DIM) {
            const float* np = g_proj + ((size_t)((t + 1) * B_DIM + b) << 8);
            float4 a0 = *(const float4*)(np + sub * 8);
            float4 a1 = *(const float4*)(np + sub * 8 + 4);
            nk[0]=a0.x; nk[1]=a0.y; nk[2]=a0.z; nk[3]=a0.w; nk[4]=a1.x; nk[5]=a1.y; nk[6]=a1.z; nk[7]=a1.w;
            float4 q0 = *(const float4*)(np + 128 + sub * 8);
            float4 q1 = *(const float4*)(np + 128 + sub * 8 + 4);
            nq[0]=q0.x; nq[1]=q0.y; nq[2]=q0.z; nq[3]=q0.w; nq[4]=q1.x; nq[5]=q1.y; nq[6]=q1.z; nq[7]=q1.w;
            float4 m0 = *(const float4*)(np + 192 + sub * 8);
            float4 m1 = *(const float4*)(np + 192 + sub * 8 + 4);
            nm[0]=m0.x; nm[1]=m0.y; nm[2]=m0.z; nm[3]=m0.w; nm[4]=m1.x; nm[5]=m1.y; nm[6]=m1.z; nm[7]=m1.w;
            nvi = np[64 + i];
            nsc = g_scal[(t + 1) * B_DIM + b];
        } else {
#pragma unroll
            for (int e = 0; e < 8; ++e) { nk[e]=0.f; nm[e]=0.f; nq[e]=0.f; }
        }

        // ---- 10 pipelined dots with NEXT vectors (independent of the chain) --
        float skp=0.f, smp=0.f, sqp=0.f, gkp=0.f, gmp=0.f;
        float kkx=0.f, kmx=0.f, kqx=0.f, mkx=0.f, mmx=0.f;
#pragma unroll
        for (int e = 0; e < 8; ++e) {
            skp = fmaf(s[e], nk[e], skp);
            smp = fmaf(s[e], nm[e], smp);
            sqp = fmaf(s[e], nq[e], sqp);
            gkp = fmaf(g[e], nk[e], gkp);
            gmp = fmaf(g[e], nm[e], gmp);
            kkx = fmaf(k[e], nk[e], kkx);
            kmx = fmaf(k[e], nm[e], kmx);
            kqx = fmaf(k[e], nq[e], kqx);
            mkx = fmaf(m[e], nk[e], mkx);
            mmx = fmaf(m[e], nm[e], mmx);
        }
#pragma unroll
        for (int o = 4; o > 0; o >>= 1) {
            skp += __shfl_xor_sync(0xffffffffu, skp, o);
            smp += __shfl_xor_sync(0xffffffffu, smp, o);
            sqp += __shfl_xor_sync(0xffffffffu, sqp, o);
            gkp += __shfl_xor_sync(0xffffffffu, gkp, o);
            gmp += __shfl_xor_sync(0xffffffffu, gmp, o);
            kkx += __shfl_xor_sync(0xffffffffu, kkx, o);
            kmx += __shfl_xor_sync(0xffffffffu, kmx, o);
            kqx += __shfl_xor_sync(0xffffffffu, kqx, o);
            mkx += __shfl_xor_sync(0xffffffffu, mkx, o);
            mmx += __shfl_xor_sync(0xffffffffu, mmx, o);
        }

        const float kk  = sc.x, mm = sc.y, kq = sc.w;
        const float kmL = LOG2E * sc.z;

        // ---- scalar-space RK4 chain (THE critical path) ----
        float A = 1.f, Bc = 0.f, Cc = 1.f, Dc = 0.f;
        float pc = p, rc = rL, uc = uL, wc = wv;
        for (int ssi = 0; ssi < ns; ++ssi) {
            float aSa = 0.f, aSb = 0.f, aGc = 0.f, aGd = 0.f;
            float as = 1.f, bs = 0.f, cc = 1.f, dc = 0.f;
#pragma unroll
            for (int st = 0; st < 4; ++st) {
                float p_st = fmaf(bs, kk,  as * pc);
                float r_st = fmaf(bs, kmL, as * rc);
                float u_st = fmaf(dc, kmL, cc * uc);
                float w_st = fmaf(dc, mm,  cc * wc);
                float dSs  = vi - p_st;
                float dGs  = dSs - w_st;
                // an = 1 - sigmoid(u) = 1/(1+e^u); gate coeff aa = -an
                float an = rcpf(1.0f + ex2f(u_st));
                float bn = rcpf(1.0f + ex2f(r_st));
                float dSa = -an * as;
                float dSb = dSs - an * bs;
                float dGc = -bn * cc;
                float dGd = dGs - bn * dc;
                float wgt = (st == 1 || st == 2) ? 2.0f : 1.0f;
                aSa = fmaf(wgt, dSa, aSa);
                aSb = fmaf(wgt, dSb, aSb);
                aGc = fmaf(wgt, dGc, aGc);
                aGd = fmaf(wgt, dGd, aGd);
                if (st < 3) {
                    float c = (st == 2) ? dt : h2;
                    as = fmaf(c, dSa, 1.0f);
                    bs = c * dSb;
                    cc = fmaf(c, dGc, 1.0f);
                    dc = c * dGd;
                }
            }
            float a_s = fmaf(hd6, aSa, 1.0f), b_s = hd6 * aSb;
            float c_g = fmaf(hd6, aGc, 1.0f), d_g = hd6 * aGd;
            A  = a_s * A;  Bc = fmaf(a_s, Bc, b_s);
            Cc = c_g * Cc; Dc = fmaf(c_g, Dc, d_g);
            pc = fmaf(b_s, kk,  a_s * pc);
            rc = fmaf(b_s, kmL, a_s * rc);
            uc = fmaf(d_g, kmL, c_g * uc);
            wc = fmaf(d_g, mm,  c_g * wc);
        }

        // ---- output: z = <s_end, q> = A*zz + B*<k,q> ----
        float z = fmaf(Bc, kq, A * zz);
        if (sub == 0) {
            out[((size_t)t * B_DIM + b) * N_DIM + i] = z * z * sigmoidf(z);
        }

        // ---- rank-1 state update (uses OLD k, m) ----
#pragma unroll
        for (int e = 0; e < 8; ++e) {
            s[e] = fmaf(A,  s[e], Bc * k[e]);
            g[e] = fmaf(Cc, g[e], Dc * m[e]);
        }

        // ---- combine pipelined dots into next chain inputs ----
        p  = fmaf(Bc, kkx, A * skp);
        rL = LOG2E * fmaf(Bc, kmx, A * smp);
        uL = LOG2E * fmaf(Dc, mkx, Cc * gkp);
        wv = fmaf(Dc, mmx, Cc * gmp);
        zz = fmaf(Bc, kqx, A * sqp);

        // ---- swap vectors ----
#pragma unroll
        for (int e = 0; e < 8; ++e) { k[e] = nk[e]; m[e] = nm[e]; }
        vi = nvi; sc = nsc;
        (void)nq;
    }

    // Final S, G: out layout = outputs [T*B*N] | S [B,N,N] | G [B,N,N]
    float* Sout = out + (size_t)T_DIM * B_DIM * N_DIM;
    float* Gout = Sout + (size_t)B_DIM * N_DIM * N_DIM;
    *(float4*)(Sout + sbase)     = make_float4(s[0], s[1], s[2], s[3]);
    *(float4*)(Sout + sbase + 4) = make_float4(s[4], s[5], s[6], s[7]);
    *(float4*)(Gout + sbase)     = make_float4(g[0], g[1], g[2], g[3]);
    *(float4*)(Gout + sbase + 4) = make_float4(g[4], g[5], g[6], g[7]);
}

// ---------------------------------------------------------------------------
extern "C" void kernel_launch(void* const* d_in, const int* in_sizes, int n_in,
                              void* d_out, int out_size) {
    const float* x  = (const float*)d_in[0];   // [T, B, 768]
    const float* S0 = (const float*)d_in[1];   // [B, 64, 64]
    const float* G0 = (const float*)d_in[2];   // [B, 64, 64]
    const float* W  = (const float*)d_in[3];   // [256, 768]
    const int*   ns = (n_in > 4) ? (const int*)d_in[4] : nullptr;
    float* out = (float*)d_out;

    dim3 ggrid(M_ROWS / 128, PROJ_C / 64);
    gemm_kernel<<<ggrid, 256>>>(x, W);

    norm_kernel<<<(M_ROWS * 32) / 256, 256>>>();

    scan_kernel<<<(B_DIM * (N_DIM / 4) * 32) / 128, 128>>>(S0, G0, ns, out);
}

// round 8
// speedup vs baseline: 1.3908x; 1.3908x over previous
#include <cuda_runtime.h>
#include <cstdint>

// Problem dims (fixed by setup_inputs)
#define T_DIM 1024
#define B_DIM 32
#define D_DIM 768
#define N_DIM 64
#define PROJ_C 256          // 4*n : k | v | q | m
#define M_ROWS (T_DIM * B_DIM)

#define LOG2E 1.4426950408889634f

// Scratch: projection results [T, B, 256] fp32 (~33.5 MB) + per-row scalars
__device__ float  g_proj[(size_t)T_DIM * B_DIM * PROJ_C];
__device__ float4 g_scal[(size_t)T_DIM * B_DIM];   // {kk, mm, km, kq}

// ---------------------------------------------------------------------------
__device__ __forceinline__ float ex2f(float x) {
    float y; asm("ex2.approx.ftz.f32 %0, %1;" : "=f"(y) : "f"(x)); return y;
}
__device__ __forceinline__ float rcpf(float x) {
    float y; asm("rcp.approx.ftz.f32 %0, %1;" : "=f"(y) : "f"(x)); return y;
}
__device__ __forceinline__ float sigmoidf(float x) {
    return rcpf(1.0f + ex2f(-x * LOG2E));
}

// ---------------------------------------------------------------------------
// GEMM: proj[r, c] = sum_d x[r, d] * W[c, d]
//   Tile: 128 (M) x 64 (N), BK = 16, 256 threads, 8x4 per-thread microtile
//   (measured at the fp32 FFMA issue roofline — leave as is)
// ---------------------------------------------------------------------------
__global__ void __launch_bounds__(256, 4)
gemm_kernel(const float* __restrict__ A, const float* __restrict__ W) {
    __shared__ float As[16][132];
    __shared__ float Bs[16][68];

    const int bm = blockIdx.x * 128;
    const int bn = blockIdx.y * 64;
    const int t  = threadIdx.x;
    const int tx = t & 15;
    const int ty = t >> 4;

    float acc[8][4];
#pragma unroll
    for (int x = 0; x < 8; ++x)
#pragma unroll
        for (int y = 0; y < 4; ++y) acc[x][y] = 0.0f;

    for (int k0 = 0; k0 < D_DIM; k0 += 16) {
#pragma unroll
        for (int p = 0; p < 2; ++p) {
            int f   = p * 256 + t;
            int row = f >> 2;
            int kq  = (f & 3) * 4;
            float4 v = *(const float4*)(A + (size_t)(bm + row) * D_DIM + k0 + kq);
            As[kq + 0][row] = v.x; As[kq + 1][row] = v.y;
            As[kq + 2][row] = v.z; As[kq + 3][row] = v.w;
        }
        {
            int row = t >> 2;
            int kq  = (t & 3) * 4;
            float4 v = *(const float4*)(W + (size_t)(bn + row) * D_DIM + k0 + kq);
            Bs[kq + 0][row] = v.x; Bs[kq + 1][row] = v.y;
            Bs[kq + 2][row] = v.z; Bs[kq + 3][row] = v.w;
        }
        __syncthreads();

#pragma unroll
        for (int kk = 0; kk < 16; ++kk) {
            float4 a0 = *(const float4*)&As[kk][ty * 8];
            float4 a1 = *(const float4*)&As[kk][ty * 8 + 4];
            float4 bv = *(const float4*)&Bs[kk][tx * 4];
            float a[8]  = {a0.x, a0.y, a0.z, a0.w, a1.x, a1.y, a1.z, a1.w};
            float bb[4] = {bv.x, bv.y, bv.z, bv.w};
#pragma unroll
            for (int x = 0; x < 8; ++x)
#pragma unroll
                for (int y = 0; y < 4; ++y)
                    acc[x][y] = fmaf(a[x], bb[y], acc[x][y]);
        }
        __syncthreads();
    }

#pragma unroll
    for (int x = 0; x < 8; ++x) {
        float4 v = make_float4(acc[x][0], acc[x][1], acc[x][2], acc[x][3]);
        *(float4*)(g_proj + (size_t)(bm + ty * 8 + x) * PROJ_C + bn + tx * 4) = v;
    }
}

// ---------------------------------------------------------------------------
// Normalize k (cols 0:64) and m (cols 192:256) per (t,b) row; also compute
// per-row scalars kk=<kn,kn>, mm=<mn,mn>, km=<kn,mn>, kq=<kn,q>.
// ---------------------------------------------------------------------------
__global__ void norm_kernel() {
    const int w    = (blockIdx.x * blockDim.x + threadIdx.x) >> 5;
    const int lane = threadIdx.x & 31;
    if (w >= M_ROWS) return;
    float* p = g_proj + (size_t)w * PROJ_C;

    float k0 = p[lane],       k1 = p[lane + 32];
    float q0 = p[128 + lane], q1 = p[160 + lane];
    float m0 = p[192 + lane], m1 = p[224 + lane];

    float sk  = fmaf(k0, k0, k1 * k1);
    float sm  = fmaf(m0, m0, m1 * m1);
    float skm = fmaf(k0, m0, k1 * m1);
    float skq = fmaf(k0, q0, k1 * q1);
#pragma unroll
    for (int o = 16; o > 0; o >>= 1) {
        float a = __shfl_xor_sync(0xffffffffu, sk,  o);
        float b = __shfl_xor_sync(0xffffffffu, sm,  o);
        float c = __shfl_xor_sync(0xffffffffu, skm, o);
        float d = __shfl_xor_sync(0xffffffffu, skq, o);
        sk += a; sm += b; skm += c; skq += d;
    }

    float ck = __fdividef(1.0f, sqrtf(sk) + 1e-6f);
    float cm = __fdividef(1.0f, sqrtf(sm) + 1e-6f);
    p[lane]       = k0 * ck;  p[lane + 32] = k1 * ck;
    p[192 + lane] = m0 * cm;  p[224 + lane] = m1 * cm;

    if (lane == 0) {
        float4 sc;
        sc.x = sk  * ck * ck;
        sc.y = sm  * cm * cm;
        sc.z = skm * ck * cm;
        sc.w = skq * ck;
        g_scal[w] = sc;
    }
}

// ---------------------------------------------------------------------------
// Sequential scan — lane-parallel scalar chains.
//
// One warp owns 8 rows of one batch. lane = row_local*4 + cb; each thread
// holds 16 contiguous elements (cols cb*16..cb*16+16) of its row's S and G.
// Per timestep:
//   chain:  the scalar-space RK4 recursion runs per-lane (each lane-quad
//           carries its OWN row's scalars — SIMD over 8 rows, 4x redundant)
//   update: s <- A*s + B*k, g <- C*g + D*m  (per-thread, 32 FMA)
//   dots:   plain <s,k'>,<s,m'>,<g,k'>,<g,m'>,<s,q'> on the UPDATED state
//           with the prefetched next vectors; 2-level butterfly (quad-local)
// Next-step vectors prefetch at iteration top and resolve under the chain.
// 256 fully independent warps.
// ---------------------------------------------------------------------------
__global__ void __launch_bounds__(64)
scan_kernel(const float* __restrict__ S0,
            const float* __restrict__ G0,
            const int*   __restrict__ ns_ptr,
            float* __restrict__ out) {
    const int w    = (blockIdx.x * blockDim.x + threadIdx.x) >> 5;   // 0..255
    const int lane = threadIdx.x & 31;
    const int b    = w >> 3;                    // 8 warps per batch
    const int rl   = lane >> 2;                 // row within warp (0..7)
    const int cb   = lane & 3;                  // column block (0..3)
    const int i    = (w & 7) * 8 + rl;          // global row 0..63
    const int cofs = cb * 16;                   // column offset

    const int   ns  = ns_ptr ? *ns_ptr : 4;
    const float dt  = __fdividef(1.0f, (float)ns);
    const float h2  = 0.5f * dt;
    const float hd6 = dt * (1.0f / 6.0f);

    // ---- load state: 16 elems each of S row and G row ----
    const size_t sbase = ((size_t)b * N_DIM + i) * N_DIM + cofs;
    float s[16], g[16];
#pragma unroll
    for (int j = 0; j < 4; ++j) {
        float4 a = *(const float4*)(S0 + sbase + j * 4);
        s[j*4+0]=a.x; s[j*4+1]=a.y; s[j*4+2]=a.z; s[j*4+3]=a.w;
        float4 c = *(const float4*)(G0 + sbase + j * 4);
        g[j*4+0]=c.x; g[j*4+1]=c.y; g[j*4+2]=c.z; g[j*4+3]=c.w;
    }

    // ---- load t=0 vectors: k, m slices (q only transient) ----
    float k[16], m[16];
    float vi;
    float4 sc;
    float p, rL, uL, wv, zz;
    {
        const float* pp = g_proj + ((size_t)b << 8);
        float q[16];
#pragma unroll
        for (int j = 0; j < 4; ++j) {
            float4 a = *(const float4*)(pp + cofs + j * 4);
            k[j*4+0]=a.x; k[j*4+1]=a.y; k[j*4+2]=a.z; k[j*4+3]=a.w;
            float4 c = *(const float4*)(pp + 192 + cofs + j * 4);
            m[j*4+0]=c.x; m[j*4+1]=c.y; m[j*4+2]=c.z; m[j*4+3]=c.w;
            float4 d = *(const float4*)(pp + 128 + cofs + j * 4);
            q[j*4+0]=d.x; q[j*4+1]=d.y; q[j*4+2]=d.z; q[j*4+3]=d.w;
        }
        vi = pp[64 + i];
        sc = g_scal[b];

        // 5 dots, 2 partial accumulators each, 2-level quad butterfly
        float d0a=0.f,d0b=0.f,d1a=0.f,d1b=0.f,d2a=0.f,d2b=0.f,d3a=0.f,d3b=0.f,d4a=0.f,d4b=0.f;
#pragma unroll
        for (int j = 0; j < 8; ++j) {
            d0a = fmaf(s[j],   k[j],   d0a);  d0b = fmaf(s[j+8], k[j+8], d0b);
            d1a = fmaf(s[j],   m[j],   d1a);  d1b = fmaf(s[j+8], m[j+8], d1b);
            d2a = fmaf(g[j],   k[j],   d2a);  d2b = fmaf(g[j+8], k[j+8], d2b);
            d3a = fmaf(g[j],   m[j],   d3a);  d3b = fmaf(g[j+8], m[j+8], d3b);
            d4a = fmaf(s[j],   q[j],   d4a);  d4b = fmaf(s[j+8], q[j+8], d4b);
        }
        float d0=d0a+d0b, d1=d1a+d1b, d2=d2a+d2b, d3=d3a+d3b, d4=d4a+d4b;
#pragma unroll
        for (int o = 1; o <= 2; o <<= 1) {
            d0 += __shfl_xor_sync(0xffffffffu, d0, o);
            d1 += __shfl_xor_sync(0xffffffffu, d1, o);
            d2 += __shfl_xor_sync(0xffffffffu, d2, o);
            d3 += __shfl_xor_sync(0xffffffffu, d3, o);
            d4 += __shfl_xor_sync(0xffffffffu, d4, o);
        }
        p = d0; rL = LOG2E * d1; uL = LOG2E * d2; wv = d3; zz = d4;
    }

    for (int t = 0; t < T_DIM; ++t) {
        // ---- prefetch vectors for t+1 (resolve under the chain) ----
        float nk[16], nm[16], q[16], nvi;
        float4 nsc;
        {
            const int tn = (t + 1 < T_DIM) ? t + 1 : t;
            const float* np = g_proj + ((size_t)(tn * B_DIM + b) << 8);
#pragma unroll
            for (int j = 0; j < 4; ++j) {
                float4 a = *(const float4*)(np + cofs + j * 4);
                nk[j*4+0]=a.x; nk[j*4+1]=a.y; nk[j*4+2]=a.z; nk[j*4+3]=a.w;
                float4 c = *(const float4*)(np + 192 + cofs + j * 4);
                nm[j*4+0]=c.x; nm[j*4+1]=c.y; nm[j*4+2]=c.z; nm[j*4+3]=c.w;
                float4 d = *(const float4*)(np + 128 + cofs + j * 4);
                q[j*4+0]=d.x; q[j*4+1]=d.y; q[j*4+2]=d.z; q[j*4+3]=d.w;
            }
            nvi = np[64 + i];
            nsc = g_scal[tn * B_DIM + b];
        }

        const float kk  = sc.x, mm = sc.y, kq = sc.w;
        const float kmL = LOG2E * sc.z;

        // ---- scalar-space RK4 chain (per-lane; SIMD across 8 rows) ----
        float A = 1.f, Bc = 0.f, Cc = 1.f, Dc = 0.f;
        float pc = p, rc = rL, uc = uL, wc = wv;
        for (int ssi = 0; ssi < ns; ++ssi) {
            float aSa = 0.f, aSb = 0.f, aGc = 0.f, aGd = 0.f;
            float as = 1.f, bs = 0.f, cc = 1.f, dc = 0.f;
#pragma unroll
            for (int st = 0; st < 4; ++st) {
                float p_st = fmaf(bs, kk,  as * pc);
                float r_st = fmaf(bs, kmL, as * rc);
                float u_st = fmaf(dc, kmL, cc * uc);
                float w_st = fmaf(dc, mm,  cc * wc);
                float dSs  = vi - p_st;
                float dGs  = dSs - w_st;
                // an = 1 - sigmoid(u) = 1/(1+e^u)  (inputs pre-scaled by log2e)
                float an = rcpf(1.0f + ex2f(u_st));
                float bn = rcpf(1.0f + ex2f(r_st));
                float dSa = -an * as;
                float dSb = dSs - an * bs;
                float dGc = -bn * cc;
                float dGd = dGs - bn * dc;
                float wgt = (st == 1 || st == 2) ? 2.0f : 1.0f;
                aSa = fmaf(wgt, dSa, aSa);
                aSb = fmaf(wgt, dSb, aSb);
                aGc = fmaf(wgt, dGc, aGc);
                aGd = fmaf(wgt, dGd, aGd);
                if (st < 3) {
                    float c = (st == 2) ? dt : h2;
                    as = fmaf(c, dSa, 1.0f);
                    bs = c * dSb;
                    cc = fmaf(c, dGc, 1.0f);
                    dc = c * dGd;
                }
            }
            float a_s = fmaf(hd6, aSa, 1.0f), b_s = hd6 * aSb;
            float c_g = fmaf(hd6, aGc, 1.0f), d_g = hd6 * aGd;
            A  = a_s * A;  Bc = fmaf(a_s, Bc, b_s);
            Cc = c_g * Cc; Dc = fmaf(c_g, Dc, d_g);
            pc = fmaf(b_s, kk,  a_s * pc);
            rc = fmaf(b_s, kmL, a_s * rc);
            uc = fmaf(d_g, kmL, c_g * uc);
            wc = fmaf(d_g, mm,  c_g * wc);
        }

        // ---- output: z = <s_end, q_t> = A*<s,q> + B*<k,q> ----
        float z = fmaf(Bc, kq, A * zz);
        if (cb == 0) {
            out[((size_t)t * B_DIM + b) * N_DIM + i] = z * z * sigmoidf(z);
        }

        // ---- state update (OLD k, m), then swap in prefetched vectors ----
#pragma unroll
        for (int j = 0; j < 16; ++j) {
            s[j] = fmaf(A,  s[j], Bc * k[j]);
            g[j] = fmaf(Cc, g[j], Dc * m[j]);
            k[j] = nk[j];
            m[j] = nm[j];
        }
        vi = nvi; sc = nsc;

        // ---- dots for t+1 on updated state with new vectors ----
        float d0a=0.f,d0b=0.f,d1a=0.f,d1b=0.f,d2a=0.f,d2b=0.f,d3a=0.f,d3b=0.f,d4a=0.f,d4b=0.f;
#pragma unroll
        for (int j = 0; j < 8; ++j) {
            d0a = fmaf(s[j],   k[j],   d0a);  d0b = fmaf(s[j+8], k[j+8], d0b);
            d1a = fmaf(s[j],   m[j],   d1a);  d1b = fmaf(s[j+8], m[j+8], d1b);
            d2a = fmaf(g[j],   k[j],   d2a);  d2b = fmaf(g[j+8], k[j+8], d2b);
            d3a = fmaf(g[j],   m[j],   d3a);  d3b = fmaf(g[j+8], m[j+8], d3b);
            d4a = fmaf(s[j],   q[j],   d4a);  d4b = fmaf(s[j+8], q[j+8], d4b);
        }
        float d0=d0a+d0b, d1=d1a+d1b, d2=d2a+d2b, d3=d3a+d3b, d4=d4a+d4b;
#pragma unroll
        for (int o = 1; o <= 2; o <<= 1) {
            d0 += __shfl_xor_sync(0xffffffffu, d0, o);
            d1 += __shfl_xor_sync(0xffffffffu, d1, o);
            d2 += __shfl_xor_sync(0xffffffffu, d2, o);
            d3 += __shfl_xor_sync(0xffffffffu, d3, o);
            d4 += __shfl_xor_sync(0xffffffffu, d4, o);
        }
        p = d0; rL = LOG2E * d1; uL = LOG2E * d2; wv = d3; zz = d4;
    }

    // Final S, G: out layout = outputs [T*B*N] | S [B,N,N] | G [B,N,N]
    float* Sout = out + (size_t)T_DIM * B_DIM * N_DIM;
    float* Gout = Sout + (size_t)B_DIM * N_DIM * N_DIM;
#pragma unroll
    for (int j = 0; j < 4; ++j) {
        *(float4*)(Sout + sbase + j * 4) = make_float4(s[j*4], s[j*4+1], s[j*4+2], s[j*4+3]);
        *(float4*)(Gout + sbase + j * 4) = make_float4(g[j*4], g[j*4+1], g[j*4+2], g[j*4+3]);
    }
}

// ---------------------------------------------------------------------------
extern "C" void kernel_launch(void* const* d_in, const int* in_sizes, int n_in,
                              void* d_out, int out_size) {
    const float* x  = (const float*)d_in[0];   // [T, B, 768]
    const float* S0 = (const float*)d_in[1];   // [B, 64, 64]
    const float* G0 = (const float*)d_in[2];   // [B, 64, 64]
    const float* W  = (const float*)d_in[3];   // [256, 768]
    const int*   ns = (n_in > 4) ? (const int*)d_in[4] : nullptr;
    float* out = (float*)d_out;

    dim3 ggrid(M_ROWS / 128, PROJ_C / 64);
    gemm_kernel<<<ggrid, 256>>>(x, W);

    norm_kernel<<<(M_ROWS * 32) / 256, 256>>>();

    // 256 warps: 8 rows per warp, lane-quad per row
    scan_kernel<<<128, 64>>>(S0, G0, ns, out);
}